// round 8
// baseline (speedup 1.0000x reference)
#include <cuda_runtime.h>
#include <cstdint>

#define NHEADS 12
#define HD 64
#define BHT 96        // B * NHEADS
#define NSEQ 1024     // H*W
#define DIM 768
#define BROWS 8192    // B * NSEQ

// ---------------- scratch (device globals; no allocation) ----------------
__device__ float g_xr[BROWS * DIM];        // tf32-rounded x
__device__ float g_w1[DIM * 3 * DIM];      // tf32-rounded qkv_w
__device__ float g_w2[DIM * DIM];          // tf32-rounded proj_w
__device__ float g_q[BHT * NSEQ * HD];     // tf32-rounded
__device__ float g_k[BHT * NSEQ * HD];     // tf32-rounded
__device__ float g_v[BHT * NSEQ * HD];     // tf32-rounded
__device__ float g_relh[BHT * 32 * 32 * 32];
__device__ float g_relw[BHT * 32 * 32 * 32];
__device__ float g_o[BROWS * DIM];         // tf32-rounded (attn epilogue)

// ---------------- tf32 helpers --------------------------------------------
__device__ __forceinline__ unsigned f2tf32(float x) {
    unsigned y;
    asm("cvt.rna.tf32.f32 %0, %1;" : "=r"(y) : "f"(x));
    return y;
}

// D += A(16x8) @ B(8x8), tf32 in (inputs pre-rounded -> raw bits exact).
__device__ __forceinline__ void mma_tf32(float* d,
                                         unsigned a0, unsigned a1, unsigned a2, unsigned a3,
                                         unsigned b0, unsigned b1)
{
    asm volatile(
        "mma.sync.aligned.m16n8k8.row.col.f32.tf32.tf32.f32 "
        "{%0,%1,%2,%3}, {%4,%5,%6,%7}, {%8,%9}, {%0,%1,%2,%3};"
        : "+f"(d[0]), "+f"(d[1]), "+f"(d[2]), "+f"(d[3])
        : "r"(a0), "r"(a1), "r"(a2), "r"(a3), "r"(b0), "r"(b1));
}

__device__ __forceinline__ void cp16(uint32_t dst, const void* src) {
    asm volatile("cp.async.cg.shared.global [%0], [%1], 16;" :: "r"(dst), "l"(src));
}

// ---------------- elementwise tf32 pre-round -------------------------------
__global__ void __launch_bounds__(256) round_kernel(
    const float* __restrict__ src, float* __restrict__ dst, int n4)
{
    int i = blockIdx.x * 256 + threadIdx.x;
    if (i < n4) {
        float4 v = ((const float4*)src)[i];
        uint4 u;
        u.x = f2tf32(v.x); u.y = f2tf32(v.y);
        u.z = f2tf32(v.z); u.w = f2tf32(v.w);
        ((uint4*)dst)[i] = u;
    }
}

// ---------------- tf32 GEMM, 3-stage cp.async pipeline ---------------------
// BM=128, BN=128, BK=16, 256 threads, warp grid 2(m) x 4(n), warp tile 64x32.
// All inputs pre-rounded to tf32 -> hot loop is pure LDS + MMA.
#define MM_AS 2560            // 128*20 floats per stage
#define MM_BS 2176            // 16*136 floats per stage
#define MM_SMEM_FLOATS (3 * (MM_AS + MM_BS))
#define MM_SMEM_BYTES  (MM_SMEM_FLOATS * 4)

template <int MODE>
__global__ void __launch_bounds__(256, 2) mm_kernel(
    const float* __restrict__ bias, float* __restrict__ C,
    int M, int N, int K)
{
    extern __shared__ float mmsm[];
    const float* A    = (MODE == 0) ? (const float*)g_o : (const float*)g_xr;
    const float* Bmat = (MODE == 0) ? (const float*)g_w2 : (const float*)g_w1;

    const int bm = blockIdx.y * 128;
    const int bn = blockIdx.x * 128;
    const int t  = threadIdx.x;
    const int w  = t >> 5;
    const int lane = t & 31;
    const int g  = lane >> 2;
    const int tg = lane & 3;
    const int wm = w >> 2;
    const int wn = w & 3;

    const int a_row = t >> 1;
    const int a_k   = (t & 1) * 8;
    const int b_k   = t >> 4;
    const int b_n   = (t & 15) * 8;

    const uint32_t sbase = (uint32_t)__cvta_generic_to_shared(mmsm);

    float acc[4][4][4];
#pragma unroll
    for (int i = 0; i < 4; i++)
#pragma unroll
        for (int j = 0; j < 4; j++)
#pragma unroll
            for (int q = 0; q < 4; q++) acc[i][j][q] = 0.f;

    const int nk = K / 16;

    auto issue = [&](int kt) {
        int buf = kt % 3;
        const float* ap = &A[(bm + a_row) * K + kt * 16 + a_k];
        uint32_t ad = sbase + (buf * MM_AS + a_row * 20 + a_k) * 4;
        cp16(ad, ap); cp16(ad + 16, ap + 4);
        const float* bp = &Bmat[(kt * 16 + b_k) * N + bn + b_n];
        uint32_t bd = sbase + (3 * MM_AS + buf * MM_BS + b_k * 136 + b_n) * 4;
        cp16(bd, bp); cp16(bd + 16, bp + 4);
        asm volatile("cp.async.commit_group;");
    };

    issue(0);
    issue(1);

    for (int kt = 0; kt < nk; kt++) {
        if (kt == nk - 1) asm volatile("cp.async.wait_group 0;");
        else              asm volatile("cp.async.wait_group 1;");
        __syncthreads();
        if (kt + 2 < nk) issue(kt + 2);

        const unsigned* as = (const unsigned*)(mmsm + (kt % 3) * MM_AS);
        const unsigned* bs = (const unsigned*)(mmsm + 3 * MM_AS + (kt % 3) * MM_BS);

#pragma unroll
        for (int ks = 0; ks < 2; ks++) {
            unsigned af[4][4];
#pragma unroll
            for (int mt = 0; mt < 4; mt++) {
                int r = wm * 64 + mt * 16 + g;
                af[mt][0] = as[r * 20 + ks * 8 + tg];
                af[mt][1] = as[(r + 8) * 20 + ks * 8 + tg];
                af[mt][2] = as[r * 20 + ks * 8 + tg + 4];
                af[mt][3] = as[(r + 8) * 20 + ks * 8 + tg + 4];
            }
            unsigned bf[4][2];
#pragma unroll
            for (int nt = 0; nt < 4; nt++) {
                int c = wn * 32 + nt * 8 + g;
                bf[nt][0] = bs[(ks * 8 + tg) * 136 + c];
                bf[nt][1] = bs[(ks * 8 + tg + 4) * 136 + c];
            }
#pragma unroll
            for (int mt = 0; mt < 4; mt++)
#pragma unroll
                for (int nt = 0; nt < 4; nt++)
                    mma_tf32(acc[mt][nt], af[mt][0], af[mt][1], af[mt][2], af[mt][3],
                             bf[nt][0], bf[nt][1]);
        }
    }

#pragma unroll
    for (int mt = 0; mt < 4; mt++) {
#pragma unroll
        for (int nt = 0; nt < 4; nt++) {
            int row = bm + wm * 64 + mt * 16 + g;
            int col = bn + wn * 32 + nt * 8 + 2 * tg;
#pragma unroll
            for (int q = 0; q < 4; q++) {
                int r = row + (q >> 1) * 8;
                int c = col + (q & 1);
                float v = acc[mt][nt][q] + bias[c];
                if (MODE == 0) {
                    C[r * N + c] = v;
                } else {
                    const int b = r >> 10;
                    const int n = r & 1023;
                    const int which = c / 768;
                    const int rem = c - which * 768;
                    const int head = rem >> 6;
                    const int d = rem & 63;
                    float* dst = (which == 0) ? g_q : (which == 1) ? g_k : g_v;
                    dst[((b * NHEADS + head) * NSEQ + n) * HD + d] =
                        __uint_as_float(f2tf32(v));
                }
            }
        }
    }
}

// ---------------- relative position bias: one block per (bh, qh) ----------
__global__ void __launch_bounds__(256) rel_kernel(
    const float* __restrict__ rph, const float* __restrict__ rpw)
{
    __shared__ float qrow[32 * 64];
    __shared__ float rh[32 * 65];
    __shared__ float rw[63 * 65];

    const int bh = blockIdx.x;
    const int qh = blockIdx.y;
    const int t  = threadIdx.x;

    for (int i = t; i < 32 * 64; i += 256) {
        int row = i >> 6, d = i & 63;
        qrow[i] = g_q[((bh * NSEQ) + qh * 32 + row) * HD + d];
        rh[row * 65 + d] = rph[(qh + row) * 64 + d];
    }
    for (int i = t; i < 63 * 64; i += 256) {
        int row = i >> 6, d = i & 63;
        rw[row * 65 + d] = rpw[i];
    }
    __syncthreads();

    for (int o = t; o < 2048; o += 256) {
        if (o < 1024) {
            int qw = o >> 5, kh = o & 31;
            const float* a  = &qrow[qw * 64];
            const float* b2 = &rh[(31 - kh) * 65];
            float s = 0.f;
#pragma unroll
            for (int d = 0; d < 64; d++) s += a[d] * b2[d];
            g_relh[(((bh * 32 + qh) * 32 + qw) * 32) + kh] = s;
        } else {
            int oo = o - 1024;
            int qw = oo >> 5, kw = oo & 31;
            const float* a  = &qrow[qw * 64];
            const float* b2 = &rw[(qw - kw + 31) * 65];
            float s = 0.f;
#pragma unroll
            for (int d = 0; d < 64; d++) s += a[d] * b2[d];
            g_relw[(((bh * 32 + qh) * 32 + qw) * 32) + kw] = s;
        }
    }
}

// ---------------- attention: QT=64 queries, KT=64 key tiles, no-max softmax
// Q/K/V values are pre-rounded to tf32 -> raw-bit copy is exact.
// smem float offsets
#define SM_QS     0                        // [64][68]  = 4352
#define SM_RELH   4352                     // [64][32]  = 2048
#define SM_RELW   6400                     // [64][32]  = 2048
#define SM_SSUM   8448                     // [4][64]   = 256
#define SM_P      8704                     // [64][68]  = 4352
#define SM_K      13056                    // [64][68]  = 4352
#define SM_V      17408                    // [64][72]  = 4608
#define ATTN_SMEM_FLOATS 22016             // 88,064 B
#define ATTN_SMEM_BYTES  (ATTN_SMEM_FLOATS * 4)

__global__ void __launch_bounds__(256, 2) attn_kernel()
{
    extern __shared__ float sm[];
    unsigned* Qu  = (unsigned*)(sm + SM_QS);
    float* RH     = sm + SM_RELH;
    float* RW     = sm + SM_RELW;
    float* SS     = sm + SM_SSUM;
    unsigned* Pu  = (unsigned*)(sm + SM_P);
    unsigned* Ku  = (unsigned*)(sm + SM_K);
    unsigned* Vu  = (unsigned*)(sm + SM_V);

    const int qt = blockIdx.x;   // 0..15 (64 q rows each)
    const int bh = blockIdx.y;   // 0..95
    const int t  = threadIdx.x;
    const int w  = t >> 5;
    const int lane = t & 31;
    const int g  = lane >> 2;
    const int tg = lane & 3;
    const int wm = w >> 2;
    const int wn = w & 3;
    const int wr = w >> 1;
    const int wd = w & 1;
    const float scale = 0.125f;

    // load Q tile (64x64, tf32-rounded bits)
#pragma unroll
    for (int f = 0; f < 4; f++) {
        int i = t + 256 * f;
        int r = i >> 4;
        int c = (i & 15) * 4;
        *(uint4*)&Qu[r * 68 + c] =
            *(const uint4*)&g_q[(bh * NSEQ + qt * 64 + r) * HD + c];
    }
    // rel bias rows for 64 q rows
    for (int i = t; i < 64 * 32; i += 256) {
        int r = i >> 5, c = i & 31;
        int qn = qt * 64 + r;
        int qh = qn >> 5, qw = qn & 31;
        int base = ((bh * 32 + qh) * 32 + qw) * 32 + c;
        RH[i] = g_relh[base];
        RW[i] = g_relw[base];
    }

    // prologue K/V prefetch (tile 0)
    uint4 kst[4], vst[4];
#pragma unroll
    for (int f = 0; f < 4; f++) {
        int fi = t + 256 * f;
        int row = fi >> 4;
        int col = (fi & 15) * 4;
        kst[f] = *(const uint4*)&g_k[(bh * NSEQ + row) * HD + col];
        vst[f] = *(const uint4*)&g_v[(bh * NSEQ + row) * HD + col];
    }

    float rsum[2][2] = {{0.f, 0.f}, {0.f, 0.f}};
    float po[4][4];
#pragma unroll
    for (int i = 0; i < 4; i++)
#pragma unroll
        for (int q = 0; q < 4; q++) po[i][q] = 0.f;

    for (int kt = 0; kt < 16; kt++) {
        // store K/V tile
#pragma unroll
        for (int f = 0; f < 4; f++) {
            int fi = t + 256 * f;
            int row = fi >> 4;
            int col = (fi & 15) * 4;
            *(uint4*)&Ku[row * 68 + col] = kst[f];
            *(uint4*)&Vu[row * 72 + col] = vst[f];
        }
        __syncthreads();   // tile ready (also covers Q/rel on kt==0)

        // prefetch next tile
        if (kt + 1 < 16) {
#pragma unroll
            for (int f = 0; f < 4; f++) {
                int fi = t + 256 * f;
                int row = fi >> 4;
                int col = (fi & 15) * 4;
                kst[f] = *(const uint4*)&g_k[(bh * NSEQ + (kt + 1) * 64 + row) * HD + col];
                vst[f] = *(const uint4*)&g_v[(bh * NSEQ + (kt + 1) * 64 + row) * HD + col];
            }
        }

        // ---- S = Q @ K^T : warp (wm,wn) owns rows wm*32+.., keys wn*16+.. --
        float acc[2][2][4];
#pragma unroll
        for (int i = 0; i < 2; i++)
#pragma unroll
            for (int j = 0; j < 2; j++)
#pragma unroll
                for (int q = 0; q < 4; q++) acc[i][j][q] = 0.f;

#pragma unroll
        for (int ks = 0; ks < 8; ks++) {
            unsigned af[2][4];
#pragma unroll
            for (int mt = 0; mt < 2; mt++) {
                int r = wm * 32 + mt * 16 + g;
                int c = ks * 8 + tg;
                af[mt][0] = Qu[r * 68 + c];
                af[mt][1] = Qu[(r + 8) * 68 + c];
                af[mt][2] = Qu[r * 68 + c + 4];
                af[mt][3] = Qu[(r + 8) * 68 + c + 4];
            }
            unsigned bf[2][2];
#pragma unroll
            for (int nt = 0; nt < 2; nt++) {
                int key = wn * 16 + nt * 8 + g;
                bf[nt][0] = Ku[key * 68 + ks * 8 + tg];
                bf[nt][1] = Ku[key * 68 + ks * 8 + tg + 4];
            }
#pragma unroll
            for (int mt = 0; mt < 2; mt++)
#pragma unroll
                for (int nt = 0; nt < 2; nt++)
                    mma_tf32(acc[mt][nt], af[mt][0], af[mt][1], af[mt][2], af[mt][3],
                             bf[nt][0], bf[nt][1]);
        }

        // ---- P = exp(scale*S + bias); accumulate private row sums ---------
#pragma unroll
        for (int mt = 0; mt < 2; mt++)
#pragma unroll
            for (int nt = 0; nt < 2; nt++)
#pragma unroll
                for (int q = 0; q < 4; q++) {
                    int rh = q >> 1;
                    int rr = wm * 32 + mt * 16 + g + rh * 8;
                    int cl = wn * 16 + nt * 8 + 2 * tg + (q & 1);
                    int cc = kt * 64 + cl;
                    int kh = cc >> 5, kw = cc & 31;
                    float e = __expf(acc[mt][nt][q] * scale
                                     + RH[rr * 32 + kh] + RW[rr * 32 + kw]);
                    rsum[mt][rh] += e;
                    Pu[rr * 68 + cl] = f2tf32(e);
                }
        __syncthreads();   // P ready

        // ---- PV: warp (wr,wd) owns rows wr*16+.., out dims wd*32+.. --------
#pragma unroll
        for (int ks = 0; ks < 8; ks++) {
            int pb = (wr * 16 + g) * 68 + ks * 8 + tg;
            unsigned a0 = Pu[pb];
            unsigned a1 = Pu[pb + 8 * 68];
            unsigned a2 = Pu[pb + 4];
            unsigned a3 = Pu[pb + 8 * 68 + 4];
#pragma unroll
            for (int nt = 0; nt < 4; nt++) {
                unsigned b0 = Vu[(ks * 8 + tg) * 72 + wd * 32 + nt * 8 + g];
                unsigned b1 = Vu[(ks * 8 + tg + 4) * 72 + wd * 32 + nt * 8 + g];
                mma_tf32(po[nt], a0, a1, a2, a3, b0, b1);
            }
        }
        __syncthreads();   // K/V/P buffers free
    }

    // ---- row-sum reduction across wn warps ---------------------------------
#pragma unroll
    for (int mt = 0; mt < 2; mt++)
#pragma unroll
        for (int rh = 0; rh < 2; rh++) {
            float v = rsum[mt][rh];
            v += __shfl_xor_sync(0xffffffffu, v, 1);
            v += __shfl_xor_sync(0xffffffffu, v, 2);
            if (tg == 0) SS[wn * 64 + wm * 32 + mt * 16 + g + rh * 8] = v;
        }
    __syncthreads();

    // ---- epilogue: normalize, round to tf32, write g_o [b][n][head][d] -----
    const int b = bh / NHEADS;
    const int head = bh % NHEADS;
    const int r0 = wr * 16 + g;
    const int r1 = r0 + 8;
    float s0 = SS[r0] + SS[64 + r0] + SS[128 + r0] + SS[192 + r0];
    float s1 = SS[r1] + SS[64 + r1] + SS[128 + r1] + SS[192 + r1];
    float i0 = 1.0f / s0;
    float i1 = 1.0f / s1;
#pragma unroll
    for (int nt = 0; nt < 4; nt++) {
        int dim = head * HD + wd * 32 + nt * 8 + 2 * tg;
        long o0 = (long)(b * NSEQ + qt * 64 + r0) * DIM + dim;
        long o1 = (long)(b * NSEQ + qt * 64 + r1) * DIM + dim;
        g_o[o0]     = __uint_as_float(f2tf32(po[nt][0] * i0));
        g_o[o0 + 1] = __uint_as_float(f2tf32(po[nt][1] * i0));
        g_o[o1]     = __uint_as_float(f2tf32(po[nt][2] * i1));
        g_o[o1 + 1] = __uint_as_float(f2tf32(po[nt][3] * i1));
    }
}

// ---------------- launch ---------------------------------------------------
extern "C" void kernel_launch(void* const* d_in, const int* in_sizes, int n_in,
                              void* d_out, int out_size)
{
    const float* x      = (const float*)d_in[0];
    const float* qkv_w  = (const float*)d_in[1];
    const float* qkv_b  = (const float*)d_in[2];
    const float* proj_w = (const float*)d_in[3];
    const float* proj_b = (const float*)d_in[4];
    const float* rph    = (const float*)d_in[5];
    const float* rpw    = (const float*)d_in[6];
    float* out = (float*)d_out;

    cudaFuncSetAttribute(attn_kernel,
                         cudaFuncAttributeMaxDynamicSharedMemorySize,
                         ATTN_SMEM_BYTES);
    cudaFuncSetAttribute(mm_kernel<1>,
                         cudaFuncAttributeMaxDynamicSharedMemorySize,
                         MM_SMEM_BYTES);
    cudaFuncSetAttribute(mm_kernel<0>,
                         cudaFuncAttributeMaxDynamicSharedMemorySize,
                         MM_SMEM_BYTES);

    float* xr = nullptr; float* w1 = nullptr; float* w2 = nullptr;
    cudaGetSymbolAddress((void**)&xr, g_xr);
    cudaGetSymbolAddress((void**)&w1, g_w1);
    cudaGetSymbolAddress((void**)&w2, g_w2);

    // 0) pre-round all GEMM inputs to tf32 (one-time elementwise pass)
    {
        int n4x = BROWS * DIM / 4;
        int n4w1 = DIM * 3 * DIM / 4;
        int n4w2 = DIM * DIM / 4;
        round_kernel<<<(n4x + 255) / 256, 256>>>(x, xr, n4x);
        round_kernel<<<(n4w1 + 255) / 256, 256>>>(qkv_w, w1, n4w1);
        round_kernel<<<(n4w2 + 255) / 256, 256>>>(proj_w, w2, n4w2);
    }

    // 1) QKV projection: (8192,768) @ (768,2304) -> scatter to q/k/v (rounded)
    mm_kernel<1><<<dim3(2304 / 128, 8192 / 128), 256, MM_SMEM_BYTES>>>(
        qkv_b, nullptr, BROWS, 3 * DIM, DIM);

    // 2) decomposed relative position bias
    rel_kernel<<<dim3(BHT, 32), 256>>>(rph, rpw);

    // 3) attention (no-max online softmax), 64-query x 64-key tiles
    attn_kernel<<<dim3(NSEQ / 64, BHT), 256, ATTN_SMEM_BYTES>>>();

    // 4) output projection: (8192,768) @ (768,768) + bias -> d_out
    mm_kernel<0><<<dim3(DIM / 128, 8192 / 128), 256, MM_SMEM_BYTES>>>(
        proj_b, out, BROWS, DIM, DIM);
}